// round 6
// baseline (speedup 1.0000x reference)
#include <cuda_runtime.h>
#include <math.h>

// Problem constants
#define B_  2048
#define T_  512
#define F_  32
#define H_  128
#define G_  512      // 4*H
#define BT  14       // batch rows per CTA -> 147 CTAs = one wave on 148 SMs
#define P_  7        // batch-row pairs per CTA
#define NT  512      // half 0: pairs 0-3, half 1: pairs 4-6
#define CWR 15       // Whh0 kg-rows cached in SMEM (of 32)

typedef unsigned long long ull;

// Slot-permuted weights as [kg][slot] float4 (coalesced LDG.128 per slot per
// k-group). slot s = q*256 + t; gate(t,q) = (t&1)*128 + q*256 + (t>>1):
// even lanes own (i_j, g_j), odd lanes own (f_j, o_j), j = t>>1.
// Padded +2 kg rows for the distance-2 prefetch.
__device__ float4 g_Wih0T4[(F_ / 4 + 2) * G_];
__device__ float4 g_Whh0T4[(H_ / 4 + 2) * G_];
__device__ float4 g_Wih1T4[(H_ / 4 + 2) * G_];
__device__ float4 g_Whh1T4[(H_ / 4 + 2) * G_];

__global__ void prep(const float* __restrict__ Wih0,
                     const float* __restrict__ Whh0,
                     const float* __restrict__ Wih1,
                     const float* __restrict__ Whh1) {
    int idx = blockIdx.x * blockDim.x + threadIdx.x;  // kg*512 + slot
    int slot = idx & 511, kg = idx >> 9;
    int t = slot & 255, q = slot >> 8;
    int gate = (t & 1) * 128 + q * 256 + (t >> 1);
    if (kg < F_ / 4)
        g_Wih0T4[kg * G_ + slot] = *(const float4*)(Wih0 + gate * F_ + 4 * kg);
    g_Whh0T4[kg * G_ + slot] = *(const float4*)(Whh0 + gate * H_ + 4 * kg);
    g_Wih1T4[kg * G_ + slot] = *(const float4*)(Wih1 + gate * H_ + 4 * kg);
    g_Whh1T4[kg * G_ + slot] = *(const float4*)(Whh1 + gate * H_ + 4 * kg);
}

__device__ __forceinline__ ull ffma2(ull a, ull b, ull c) {
    ull d;
    asm("fma.rn.f32x2 %0, %1, %2, %3;" : "=l"(d) : "l"(a), "l"(b), "l"(c));
    return d;
}
__device__ __forceinline__ ull dup2(float w) {
    ull d;
    asm("mov.b64 %0, {%1, %1};" : "=l"(d) : "f"(w));
    return d;
}
__device__ __forceinline__ float2 u2f(ull v) {
    float2 r;
    asm("mov.b64 {%0, %1}, %2;" : "=f"(r.x), "=f"(r.y) : "l"(v));
    return r;
}
__device__ __forceinline__ ull f2u(float2 v) {
    ull r;
    asm("mov.b64 %0, {%1, %2};" : "=l"(r) : "f"(v.x), "f"(v.y));
    return r;
}
__device__ __forceinline__ float sigm(float x) {
    return 1.0f / (1.0f + __expf(-x));
}
__device__ __forceinline__ float tanh_f(float x) {
    float e = __expf(-2.0f * fabsf(x));
    float t = (1.0f - e) / (1.0f + e);
    return x >= 0.0f ? t : -t;
}

// Inner k-group body: z[q][p] += hpair[p][4kg..4kg+3] * w{a,b}
template <int KDIM, int NP>
__device__ __forceinline__ void kbody(float4 wa, float4 wb,
                                      const float2* __restrict__ hp,
                                      ull z[2][NP], int kidx) {
    ull a0 = dup2(wa.x), a1 = dup2(wa.y), a2 = dup2(wa.z), a3 = dup2(wa.w);
    ull b0 = dup2(wb.x), b1 = dup2(wb.y), b2 = dup2(wb.z), b3 = dup2(wb.w);
#pragma unroll
    for (int p = 0; p < NP; ++p) {
        const ulonglong2* hv = (const ulonglong2*)(hp + p * KDIM) + 2 * kidx;
        ulonglong2 v0 = hv[0];
        ulonglong2 v1 = hv[1];
        ull z0 = z[0][p], z1 = z[1][p];
        z0 = ffma2(v0.x, a0, z0);
        z0 = ffma2(v0.y, a1, z0);
        z0 = ffma2(v1.x, a2, z0);
        z0 = ffma2(v1.y, a3, z0);
        z1 = ffma2(v0.x, b0, z1);
        z1 = ffma2(v0.y, b1, z1);
        z1 = ffma2(v1.x, b2, z1);
        z1 = ffma2(v1.y, b3, z1);
        z[0][p] = z0; z[1][p] = z1;
    }
}

// GEMM panel, weights streamed from global with distance-2 prefetch.
template <int KDIM, int KG, int NP>
__device__ __forceinline__ void gemm_g(const float4* __restrict__ W4,
                                       const float2* __restrict__ hp,
                                       int kbase, ull z[2][NP], int g0) {
    const float4* pA = W4 + g0;
    const float4* pB = W4 + g0 + 256;
    float4 wa0 = pA[0], wa1 = pA[G_];
    float4 wb0 = pB[0], wb1 = pB[G_];
#pragma unroll 1
    for (int kg = 0; kg < KG; ++kg) {
        float4 na = pA[(size_t)(kg + 2) * G_];
        float4 nb = pB[(size_t)(kg + 2) * G_];
        kbody<KDIM, NP>(wa0, wb0, hp, z, kbase + kg);
        wa0 = wa1; wa1 = na;
        wb0 = wb1; wb1 = nb;
    }
}

// GEMM panel, weights from SMEM cache.
template <int KDIM, int KG, int NP>
__device__ __forceinline__ void gemm_s(const float4* __restrict__ Ws,
                                       const float2* __restrict__ hp,
                                       int kbase, ull z[2][NP], int g0) {
#pragma unroll 1
    for (int kg = 0; kg < KG; ++kg) {
        float4 wa = Ws[kg * G_ + g0];
        float4 wb = Ws[kg * G_ + g0 + 256];
        kbody<KDIM, NP>(wa, wb, hp, z, kbase + kg);
    }
}

// Fused gate update: even lane holds (z_i, z_g), odd lane (z_f, z_o).
// Uniform math: tanh(x) = 2*sigm(2x)-1, selects instead of divergence.
// Odd lane keeps c in registers and writes h for output j.
template <int NP>
__device__ __forceinline__ void gate_update(ull z[2][NP], ull c[NP],
                                            float2* __restrict__ hout,
                                            int j, bool evn) {
#pragma unroll
    for (int p = 0; p < NP; ++p) {
        float2 zA = u2f(z[0][p]);   // i (even) / f (odd)
        float2 zB = u2f(z[1][p]);   // g (even) / o (odd)
        float bx = evn ? 2.0f * zB.x : zB.x;
        float by = evn ? 2.0f * zB.y : zB.y;
        float aAx = sigm(zA.x), aAy = sigm(zA.y);
        float ex = sigm(bx), ey = sigm(by);
        float aBx = evn ? 2.0f * ex - 1.0f : ex;   // g=tanh / o=sigm
        float aBy = evn ? 2.0f * ey - 1.0f : ey;
        float sx = evn ? aAx * aBx : aAx;          // even sends i*g, odd sends f
        float sy = evn ? aAy * aBy : aAy;
        float rx = __shfl_xor_sync(0xffffffffu, sx, 1);
        float ry = __shfl_xor_sync(0xffffffffu, sy, 1);
        float2 cc = u2f(c[p]);
        cc.x = sx * cc.x + rx;     // odd: f*c + i*g   (garbage on even, unused)
        cc.y = sy * cc.y + ry;
        c[p] = f2u(cc);
        float hx = aBx * tanh_f(cc.x);   // odd: o * tanh(c)
        float hy = aBy * tanh_f(cc.y);
        if (!evn) hout[p * H_ + j] = make_float2(hx, hy);
    }
}

extern __shared__ float4 smem4[];

template <int NP>
__device__ __forceinline__ void step_both_layers(
    const float4* __restrict__ sWih0, const float4* __restrict__ sWhh0,
    const float2* __restrict__ xin,
    const float2* __restrict__ h0in, float2* __restrict__ h0out,
    const float2* __restrict__ h1in, float2* __restrict__ h1out,
    ull bias0a, ull bias0b, ull bias1a, ull bias1b,
    ull c0[NP], ull c1[NP], int g0, int j, bool evn,
    const float* __restrict__ x, float2* __restrict__ xnext,
    int t, int b_base, int nb, int tid) {
    // ---- layer 0 ----
    ull z[2][NP];
#pragma unroll
    for (int p = 0; p < NP; ++p) { z[0][p] = bias0a; z[1][p] = bias0b; }
    gemm_s<F_, F_ / 4, NP>(sWih0, xin, 0, z, g0);
    gemm_s<H_, CWR, NP>(sWhh0, h0in, 0, z, g0);
    gemm_g<H_, H_ / 4 - CWR, NP>(g_Whh0T4 + CWR * G_, h0in, CWR, z, g0);
    gate_update<NP>(z, c0, h0out, j, evn);

    // stage x(t+1) while layer-0 results settle
    if (t + 1 < T_) {
        for (int i = tid; i < BT * F_; i += NT) {
            int b = i / F_, f = i % F_;
            float v = (b < nb)
                ? x[((size_t)(b_base + b) * T_ + (t + 1)) * F_ + f]
                : 0.0f;
            ((float*)xnext)[(b >> 1) * F_ * 2 + f * 2 + (b & 1)] = v;
        }
    }
    __syncthreads();

    // ---- layer 1 ----
#pragma unroll
    for (int p = 0; p < NP; ++p) { z[0][p] = bias1a; z[1][p] = bias1b; }
    gemm_g<H_, H_ / 4, NP>(g_Wih1T4, h0out, 0, z, g0);
    gemm_g<H_, H_ / 4, NP>(g_Whh1T4, h1in, 0, z, g0);
    gate_update<NP>(z, c1, h1out, j, evn);
    __syncthreads();
}

__global__ void __launch_bounds__(NT, 1)
lstm_persistent(const float* __restrict__ x,
                const float* __restrict__ b0,
                const float* __restrict__ b1,
                const float* __restrict__ Wfc,
                const float* __restrict__ bfc,
                float* __restrict__ out) {
    // SMEM: [Wih0 cache 8 rows][Whh0 cache CWR rows][h0 x2][h1 x2][x x2]
    float4* sWih0 = smem4;                            // 8*G_
    float4* sWhh0 = smem4 + (F_ / 4) * G_;            // CWR*G_
    float2* hbase = (float2*)(smem4 + (F_ / 4 + CWR) * G_);
    float2* h0b[2] = { hbase,              hbase + P_ * H_ };
    float2* h1b[2] = { hbase + 2 * P_ * H_, hbase + 3 * P_ * H_ };
    float2* xb[2]  = { hbase + 4 * P_ * H_, hbase + 4 * P_ * H_ + P_ * F_ };

    const int tid = threadIdx.x;
    const int g0 = tid & 255;            // slots g0 and g0+256
    const int half = tid >> 8;           // 0: pairs 0-3, 1: pairs 4-6
    const int j = g0 >> 1;               // output index for this lane pair
    const bool evn = (g0 & 1) == 0;
    const int b_base = blockIdx.x * BT;
    const int nb = min(BT, B_ - b_base);

    // fill weight caches (once per launch)
    for (int i = tid; i < (F_ / 4) * G_; i += NT) sWih0[i] = g_Wih0T4[i];
    for (int i = tid; i < CWR * G_; i += NT) sWhh0[i] = g_Whh0T4[i];
    // zero h buffers
    for (int i = tid; i < 4 * P_ * H_; i += NT) hbase[i] = make_float2(0.f, 0.f);
    // stage x(t=0)
    for (int i = tid; i < BT * F_; i += NT) {
        int b = i / F_, f = i % F_;
        float v = (b < nb) ? x[((size_t)(b_base + b) * T_) * F_ + f] : 0.0f;
        ((float*)xb[0])[(b >> 1) * F_ * 2 + f * 2 + (b & 1)] = v;
    }

    const int gateA = (g0 & 1) * 128 + (g0 >> 1);
    const ull bias0a = dup2(b0[gateA]);
    const ull bias0b = dup2(b0[gateA + 256]);
    const ull bias1a = dup2(b1[gateA]);
    const ull bias1b = dup2(b1[gateA + 256]);

    ull c0[4], c1[4];
#pragma unroll
    for (int p = 0; p < 4; ++p) { c0[p] = 0ull; c1[p] = 0ull; }

    __syncthreads();

    int cur = 0;
    for (int t = 0; t < T_; ++t) {
        if (half == 0) {
            step_both_layers<4>(sWih0, sWhh0,
                                xb[cur], h0b[cur], h0b[cur ^ 1],
                                h1b[cur], h1b[cur ^ 1],
                                bias0a, bias0b, bias1a, bias1b,
                                c0, c1, g0, j, evn,
                                x, xb[cur ^ 1], t, b_base, nb, tid);
        } else {
            step_both_layers<3>(sWih0, sWhh0,
                                xb[cur] + 4 * F_,
                                h0b[cur] + 4 * H_, h0b[cur ^ 1] + 4 * H_,
                                h1b[cur] + 4 * H_, h1b[cur ^ 1] + 4 * H_,
                                bias0a, bias0b, bias1a, bias1b,
                                c0, c1, g0, j, evn,
                                x, xb[cur ^ 1], t, b_base, nb, tid);
        }
        cur ^= 1;
    }

    // FC head: h1b[cur] holds h1(T-1)
    if (tid < nb) {
        const float2* hf = h1b[cur] + (tid >> 1) * H_;
        float s = bfc[0];
        int sel = tid & 1;
#pragma unroll
        for (int k = 0; k < H_; ++k) {
            float2 hv = hf[k];
            s = fmaf(sel ? hv.y : hv.x, Wfc[k], s);
        }
        out[b_base + tid] = s;
    }
}

extern "C" void kernel_launch(void* const* d_in, const int* in_sizes, int n_in,
                              void* d_out, int out_size) {
    const float* x    = (const float*)d_in[0];
    const float* Wih0 = (const float*)d_in[1];
    const float* Whh0 = (const float*)d_in[2];
    const float* b0   = (const float*)d_in[3];
    const float* Wih1 = (const float*)d_in[4];
    const float* Whh1 = (const float*)d_in[5];
    const float* b1   = (const float*)d_in[6];
    const float* Wfc  = (const float*)d_in[7];
    const float* bfc  = (const float*)d_in[8];
    float* out = (float*)d_out;
    (void)in_sizes; (void)n_in; (void)out_size;

    prep<<<(G_ * (H_ / 4)) / 256, 256>>>(Wih0, Whh0, Wih1, Whh1);

    const int smem_bytes =
        (F_ / 4 + CWR) * G_ * (int)sizeof(float4) +   // weight caches
        4 * P_ * H_ * (int)sizeof(float2) +           // h double buffers
        2 * P_ * F_ * (int)sizeof(float2);            // x double buffer
    cudaFuncSetAttribute(lstm_persistent,
                         cudaFuncAttributeMaxDynamicSharedMemorySize,
                         smem_bytes);

    lstm_persistent<<<(B_ + BT - 1) / BT, NT, smem_bytes>>>(
        x, b0, b1, Wfc, bfc, out);
}

// round 7
// speedup vs baseline: 1.4774x; 1.4774x over previous
#include <cuda_runtime.h>
#include <math.h>

// Problem constants
#define B_  2048
#define T_  512
#define F_  32
#define H_  128
#define G_  512      // 4*H
#define BT  14       // batch rows per CTA -> 147 CTAs = one wave on 148 SMs
#define P_  7        // batch-row pairs per CTA (each thread handles all 7)
#define NT  512      // half 0: k in [0,64); half 1: k in [64,128)
#define PST 9        // zbuf pair stride in ull
#define CWHH 6       // Whh0 kg-rows cached in SMEM (rows 0..5)

typedef unsigned long long ull;

// Weights as [kg][gate] float4: coalesced LDG.128 per gate per k-group.
// Padded +2 kg rows for the distance-2 prefetch.
__device__ float4 g_Wih0T4[(F_ / 4 + 2) * G_];
__device__ float4 g_Whh0T4[(H_ / 4 + 2) * G_];
__device__ float4 g_Wih1T4[(H_ / 4 + 2) * G_];
__device__ float4 g_Whh1T4[(H_ / 4 + 2) * G_];

__global__ void prep(const float* __restrict__ Wih0,
                     const float* __restrict__ Whh0,
                     const float* __restrict__ Wih1,
                     const float* __restrict__ Whh1) {
    int idx = blockIdx.x * blockDim.x + threadIdx.x;  // 0 .. 512*32-1
    int g = idx >> 5, kg = idx & 31;
    if (kg < F_ / 4)
        g_Wih0T4[kg * G_ + g] = *(const float4*)(Wih0 + g * F_ + 4 * kg);
    g_Whh0T4[kg * G_ + g] = *(const float4*)(Whh0 + g * H_ + 4 * kg);
    g_Wih1T4[kg * G_ + g] = *(const float4*)(Wih1 + g * H_ + 4 * kg);
    g_Whh1T4[kg * G_ + g] = *(const float4*)(Whh1 + g * H_ + 4 * kg);
}

__device__ __forceinline__ ull ffma2(ull a, ull b, ull c) {
    ull d;
    asm("fma.rn.f32x2 %0, %1, %2, %3;" : "=l"(d) : "l"(a), "l"(b), "l"(c));
    return d;
}
__device__ __forceinline__ ull dup2(float w) {
    ull d;
    asm("mov.b64 %0, {%1, %1};" : "=l"(d) : "f"(w));
    return d;
}
__device__ __forceinline__ ull pack2(float lo, float hi) {
    return (ull)__float_as_uint(lo) | ((ull)__float_as_uint(hi) << 32);
}
__device__ __forceinline__ float2 u2f(ull v) {
    float2 r;
    asm("mov.b64 {%0, %1}, %2;" : "=f"(r.x), "=f"(r.y) : "l"(v));
    return r;
}
__device__ __forceinline__ float sigm(float x) {
    return 1.0f / (1.0f + __expf(-x));
}
__device__ __forceinline__ float tanh_f(float x) {
    float e = __expf(-2.0f * fabsf(x));
    float t = (1.0f - e) / (1.0f + e);
    return x >= 0.0f ? t : -t;
}

// Inner k-group body: z[q][p] += hpair[p][4k..4k+3] * w{a,b}, kidx absolute.
template <int KDIM>
__device__ __forceinline__ void kbody(float4 wa, float4 wb,
                                      const float2* __restrict__ hp,
                                      ull z[2][P_], int kidx) {
    ull a0 = dup2(wa.x), a1 = dup2(wa.y), a2 = dup2(wa.z), a3 = dup2(wa.w);
    ull b0 = dup2(wb.x), b1 = dup2(wb.y), b2 = dup2(wb.z), b3 = dup2(wb.w);
#pragma unroll
    for (int p = 0; p < P_; ++p) {
        const ulonglong2* hv = (const ulonglong2*)(hp + p * KDIM) + 2 * kidx;
        ulonglong2 v0 = hv[0];
        ulonglong2 v1 = hv[1];
        ull z0 = z[0][p], z1 = z[1][p];
        z0 = ffma2(v0.x, a0, z0);
        z0 = ffma2(v0.y, a1, z0);
        z0 = ffma2(v1.x, a2, z0);
        z0 = ffma2(v1.y, a3, z0);
        z1 = ffma2(v0.x, b0, z1);
        z1 = ffma2(v0.y, b1, z1);
        z1 = ffma2(v1.x, b2, z1);
        z1 = ffma2(v1.y, b3, z1);
        z[0][p] = z0; z[1][p] = z1;
    }
}

// GEMM panel over KG k-groups starting at absolute kg index kbase.
// W4 already points at the kbase row. Distance-2 rolling prefetch (arrays
// padded / mid-array reads are valid).
template <int KDIM, int KG>
__device__ __forceinline__ void gemm_g(const float4* __restrict__ W4,
                                       const float2* __restrict__ hp,
                                       int kbase, ull z[2][P_], int g0) {
    const float4* pA = W4 + g0;
    const float4* pB = W4 + g0 + 256;
    float4 wa0 = pA[0], wa1 = pA[G_];
    float4 wb0 = pB[0], wb1 = pB[G_];
#pragma unroll 1
    for (int kg = 0; kg < KG; ++kg) {
        float4 na = pA[(size_t)(kg + 2) * G_];
        float4 nb = pB[(size_t)(kg + 2) * G_];
        kbody<KDIM>(wa0, wb0, hp, z, kbase + kg);
        wa0 = wa1; wa1 = na;
        wb0 = wb1; wb1 = nb;
    }
}

// GEMM panel from SMEM cache.
template <int KDIM, int KG>
__device__ __forceinline__ void gemm_s(const float4* __restrict__ Ws,
                                       const float2* __restrict__ hp,
                                       int kbase, ull z[2][P_], int g0) {
#pragma unroll 1
    for (int kg = 0; kg < KG; ++kg) {
        float4 wa = Ws[kg * G_ + g0];
        float4 wb = Ws[kg * G_ + g0 + 256];
        kbody<KDIM>(wa, wb, hp, z, kbase + kg);
    }
}

extern __shared__ float4 smem4[];

__global__ void __launch_bounds__(NT, 1)
lstm_persistent(const float* __restrict__ x,
                const float* __restrict__ b0,
                const float* __restrict__ b1,
                const float* __restrict__ Wfc,
                const float* __restrict__ bfc,
                float* __restrict__ out) {
    // SMEM: [Wih0 cache 8 rows][Whh0 cache CWHH rows][h0,c0,h1,c1][zbuf x2][x x2]
    float4* sWih0 = smem4;                            // 8*G_
    float4* sWhh0 = smem4 + (F_ / 4) * G_;            // CWHH*G_
    float2* hbase = (float2*)(smem4 + (F_ / 4 + CWHH) * G_);
    float2* h0p = hbase;                 // P_*H_
    float2* c0p = h0p + P_ * H_;
    float2* h1p = c0p + P_ * H_;
    float2* c1p = h1p + P_ * H_;
    ull* zbu0 = (ull*)(c1p + P_ * H_);   // G_*PST (half 0 partials)
    ull* zbu1 = zbu0 + G_ * PST;         // G_*PST (half 1 partials)
    float2* xb[2] = { (float2*)(zbu1 + G_ * PST),
                      (float2*)(zbu1 + G_ * PST) + P_ * F_ };

    const int tid = threadIdx.x;
    const int g0 = tid & 255;            // gates g0 and g0+256
    const int half = tid >> 8;           // 0: k [0,64), 1: k [64,128)
    const int b_base = blockIdx.x * BT;
    const int nb = min(BT, B_ - b_base);
    ull* zmy = half ? zbu1 : zbu0;

    // fill weight caches (once per launch)
    for (int i = tid; i < (F_ / 4) * G_; i += NT) sWih0[i] = g_Wih0T4[i];
    for (int i = tid; i < CWHH * G_; i += NT) sWhh0[i] = g_Whh0T4[i];
    // zero h/c
    for (int i = tid; i < 4 * P_ * H_; i += NT) hbase[i] = make_float2(0.f, 0.f);
    // stage x(t=0)
    for (int i = tid; i < BT * F_; i += NT) {
        int b = i / F_, f = i % F_;
        float v = (b < nb) ? x[((size_t)(b_base + b) * T_) * F_ + f] : 0.0f;
        ((float*)xb[0])[(b >> 1) * F_ * 2 + f * 2 + (b & 1)] = v;
    }

    // biases only in half 0's partial
    const ull bias0a = half ? 0ull : pack2(b0[g0], b0[g0]);
    const ull bias0b = half ? 0ull : pack2(b0[g0 + 256], b0[g0 + 256]);
    const ull bias1a = half ? 0ull : pack2(b1[g0], b1[g0]);
    const ull bias1b = half ? 0ull : pack2(b1[g0 + 256], b1[g0 + 256]);
    __syncthreads();

    int cur = 0;
    for (int t = 0; t < T_; ++t) {
        // ---------- layer 0 GEMM (split-K across halves) ----------
        ull z[2][P_];
#pragma unroll
        for (int p = 0; p < P_; ++p) { z[0][p] = bias0a; z[1][p] = bias0b; }
        if (half == 0) {
            gemm_s<F_, 4>(sWih0, xb[cur], 0, z, g0);
            gemm_s<H_, CWHH>(sWhh0, h0p, 0, z, g0);
            gemm_g<H_, 16 - CWHH>(g_Whh0T4 + CWHH * G_, h0p, CWHH, z, g0);
        } else {
            gemm_s<F_, 4>(sWih0 + 4 * G_, xb[cur], 4, z, g0);
            gemm_g<H_, 16>(g_Whh0T4 + 16 * G_, h0p, 16, z, g0);
        }
#pragma unroll
        for (int p = 0; p < P_; ++p) {
            zmy[g0 * PST + p] = z[0][p];
            zmy[(g0 + 256) * PST + p] = z[1][p];
        }
        __syncthreads();

        // ---------- layer 0 gate update (sums partials) ----------
        for (int i = tid; i < P_ * H_; i += NT) {
            int p = i >> 7, j = i & (H_ - 1);
            float2 ziA = u2f(zbu0[(j      ) * PST + p]);
            float2 ziB = u2f(zbu1[(j      ) * PST + p]);
            float2 zfA = u2f(zbu0[(j + 128) * PST + p]);
            float2 zfB = u2f(zbu1[(j + 128) * PST + p]);
            float2 zgA = u2f(zbu0[(j + 256) * PST + p]);
            float2 zgB = u2f(zbu1[(j + 256) * PST + p]);
            float2 zoA = u2f(zbu0[(j + 384) * PST + p]);
            float2 zoB = u2f(zbu1[(j + 384) * PST + p]);
            float zix = ziA.x + ziB.x, ziy = ziA.y + ziB.y;
            float zfx = zfA.x + zfB.x, zfy = zfA.y + zfB.y;
            float zgx = zgA.x + zgB.x, zgy = zgA.y + zgB.y;
            float zox = zoA.x + zoB.x, zoy = zoA.y + zoB.y;
            float2 c = c0p[p * H_ + j];
            float2 nc, nh;
            nc.x = sigm(zfx) * c.x + sigm(zix) * tanh_f(zgx);
            nc.y = sigm(zfy) * c.y + sigm(ziy) * tanh_f(zgy);
            nh.x = sigm(zox) * tanh_f(nc.x);
            nh.y = sigm(zoy) * tanh_f(nc.y);
            c0p[p * H_ + j] = nc;
            h0p[p * H_ + j] = nh;
        }
        __syncthreads();

        // ---------- layer 1 GEMM (split-K) ----------
#pragma unroll
        for (int p = 0; p < P_; ++p) { z[0][p] = bias1a; z[1][p] = bias1b; }
        if (half == 0) {
            gemm_g<H_, 16>(g_Wih1T4, h0p, 0, z, g0);
            gemm_g<H_, 16>(g_Whh1T4, h1p, 0, z, g0);
        } else {
            gemm_g<H_, 16>(g_Wih1T4 + 16 * G_, h0p, 16, z, g0);
            gemm_g<H_, 16>(g_Whh1T4 + 16 * G_, h1p, 16, z, g0);
        }
#pragma unroll
        for (int p = 0; p < P_; ++p) {
            zmy[g0 * PST + p] = z[0][p];
            zmy[(g0 + 256) * PST + p] = z[1][p];
        }
        // stage x(t+1) into the other buffer while z settles
        if (t + 1 < T_) {
            for (int i = tid; i < BT * F_; i += NT) {
                int b = i / F_, f = i % F_;
                float v = (b < nb)
                    ? x[((size_t)(b_base + b) * T_ + (t + 1)) * F_ + f]
                    : 0.0f;
                ((float*)xb[cur ^ 1])[(b >> 1) * F_ * 2 + f * 2 + (b & 1)] = v;
            }
        }
        __syncthreads();

        // ---------- layer 1 gate update ----------
        for (int i = tid; i < P_ * H_; i += NT) {
            int p = i >> 7, j = i & (H_ - 1);
            float2 ziA = u2f(zbu0[(j      ) * PST + p]);
            float2 ziB = u2f(zbu1[(j      ) * PST + p]);
            float2 zfA = u2f(zbu0[(j + 128) * PST + p]);
            float2 zfB = u2f(zbu1[(j + 128) * PST + p]);
            float2 zgA = u2f(zbu0[(j + 256) * PST + p]);
            float2 zgB = u2f(zbu1[(j + 256) * PST + p]);
            float2 zoA = u2f(zbu0[(j + 384) * PST + p]);
            float2 zoB = u2f(zbu1[(j + 384) * PST + p]);
            float zix = ziA.x + ziB.x, ziy = ziA.y + ziB.y;
            float zfx = zfA.x + zfB.x, zfy = zfA.y + zfB.y;
            float zgx = zgA.x + zgB.x, zgy = zgA.y + zgB.y;
            float zox = zoA.x + zoB.x, zoy = zoA.y + zoB.y;
            float2 c = c1p[p * H_ + j];
            float2 nc, nh;
            nc.x = sigm(zfx) * c.x + sigm(zix) * tanh_f(zgx);
            nc.y = sigm(zfy) * c.y + sigm(ziy) * tanh_f(zgy);
            nh.x = sigm(zox) * tanh_f(nc.x);
            nh.y = sigm(zoy) * tanh_f(nc.y);
            c1p[p * H_ + j] = nc;
            h1p[p * H_ + j] = nh;
        }
        __syncthreads();
        cur ^= 1;
    }

    // FC head
    if (tid < nb) {
        float s = bfc[0];
#pragma unroll
        for (int k = 0; k < H_; ++k) {
            float2 hv = h1p[(tid >> 1) * H_ + k];
            float h = (tid & 1) ? hv.y : hv.x;
            s = fmaf(h, Wfc[k], s);
        }
        out[b_base + tid] = s;
    }
}

extern "C" void kernel_launch(void* const* d_in, const int* in_sizes, int n_in,
                              void* d_out, int out_size) {
    const float* x    = (const float*)d_in[0];
    const float* Wih0 = (const float*)d_in[1];
    const float* Whh0 = (const float*)d_in[2];
    const float* b0   = (const float*)d_in[3];
    const float* Wih1 = (const float*)d_in[4];
    const float* Whh1 = (const float*)d_in[5];
    const float* b1   = (const float*)d_in[6];
    const float* Wfc  = (const float*)d_in[7];
    const float* bfc  = (const float*)d_in[8];
    float* out = (float*)d_out;
    (void)in_sizes; (void)n_in; (void)out_size;

    prep<<<(G_ * (H_ / 4)) / 256, 256>>>(Wih0, Whh0, Wih1, Whh1);

    const int smem_bytes =
        (F_ / 4 + CWHH) * G_ * (int)sizeof(float4) +   // weight caches
        4 * P_ * H_ * (int)sizeof(float2) +            // h/c
        2 * G_ * PST * (int)sizeof(ull) +              // split-K zbufs
        2 * P_ * F_ * (int)sizeof(float2);             // x double buffer
    cudaFuncSetAttribute(lstm_persistent,
                         cudaFuncAttributeMaxDynamicSharedMemorySize,
                         smem_bytes);

    lstm_persistent<<<(B_ + BT - 1) / BT, NT, smem_bytes>>>(
        x, b0, b1, Wfc, bfc, out);
}